// round 2
// baseline (speedup 1.0000x reference)
#include <cuda_runtime.h>
#include <cuda_bf16.h>
#include <math.h>

// ---------------------------------------------------------------------------
// Problem constants (shapes fixed by the reference)
// ---------------------------------------------------------------------------
#define HID    512
#define GATES  2048      // 4*HID
#define MAXLEN 128
#define BMAX   1024
#define TMAX   (BMAX * 127)   // 130048 max ragged tokens

// ---------------------------------------------------------------------------
// Scratch (static __device__ arrays; no allocation allowed)
// ---------------------------------------------------------------------------
__device__ float g_x1[(size_t)TMAX * HID];        // encoder layer 0 out
__device__ float g_x2[(size_t)TMAX * HID];        // encoder layer 1 out
__device__ float g_xproj[(size_t)TMAX * GATES];   // x @ Wih^T  (no bias)
__device__ float g_h0[BMAX * HID];
__device__ float g_h1[BMAX * HID];
__device__ float g_c [BMAX * HID];
__device__ float g_t0[BMAX * HID];
__device__ float g_t1[BMAX * HID];
__device__ int   g_starts[BMAX];

// ---------------------------------------------------------------------------
// starts[b] = exclusive prefix sum of segment sizes
// ---------------------------------------------------------------------------
__global__ void scan_starts_kernel(const int* __restrict__ sizes, int* __restrict__ starts, int B) {
    __shared__ int s[BMAX];
    int tid = threadIdx.x;
    if (tid < B) s[tid] = sizes[tid];
    __syncthreads();
    if (tid == 0) {
        int acc = 0;
        for (int i = 0; i < B; i++) { starts[i] = acc; acc += s[i]; }
    }
}

__global__ void fill_zero_kernel(float* __restrict__ p, int n) {
    int i = blockIdx.x * blockDim.x + threadIdx.x;
    if (i < n) p[i] = 0.f;
}

// ---------------------------------------------------------------------------
// Generic NT GEMM:  C[M,N] = act( A[M,K] @ B[N,K]^T + bias[N] ) (+ R[M,N])
//   mode 0: none     mode 1: relu     mode 2: relu + residual R
// Tiles: 64x64x16, 256 threads, 4x4 micro-tile per thread.
// ---------------------------------------------------------------------------
#define BM 64
#define BN 64
#define BK 16

__global__ __launch_bounds__(256) void gemm_nt_kernel(
    const float* __restrict__ A, const float* __restrict__ B,
    const float* __restrict__ bias, const float* __restrict__ R,
    float* __restrict__ C, int M, int N, int K, int mode)
{
    __shared__ float As[BK][BM];
    __shared__ float Bs[BK][BN];

    const int m0 = blockIdx.y * BM;
    const int n0 = blockIdx.x * BN;
    const int tid = threadIdx.x;
    const int tx = tid & 15;        // 0..15
    const int ty = tid >> 4;        // 0..15
    const int lrow = tid >> 2;      // 0..63
    const int lkq  = (tid & 3) * 4; // 0,4,8,12

    float acc[4][4] = {};

    for (int k0 = 0; k0 < K; k0 += BK) {
        // --- load A tile (transposed into smem) ---
        {
            float4 v = make_float4(0.f, 0.f, 0.f, 0.f);
            int gm = m0 + lrow;
            int gk = k0 + lkq;
            if (gm < M) {
                if (gk + 3 < K) {
                    v = *reinterpret_cast<const float4*>(A + (size_t)gm * K + gk);
                } else {
                    float t[4] = {0.f, 0.f, 0.f, 0.f};
                    #pragma unroll
                    for (int q = 0; q < 4; q++) if (gk + q < K) t[q] = A[(size_t)gm * K + gk + q];
                    v = make_float4(t[0], t[1], t[2], t[3]);
                }
            }
            As[lkq + 0][lrow] = v.x; As[lkq + 1][lrow] = v.y;
            As[lkq + 2][lrow] = v.z; As[lkq + 3][lrow] = v.w;
        }
        // --- load B tile ---
        {
            float4 v = make_float4(0.f, 0.f, 0.f, 0.f);
            int gn = n0 + lrow;
            int gk = k0 + lkq;
            if (gn < N) {
                if (gk + 3 < K) {
                    v = *reinterpret_cast<const float4*>(B + (size_t)gn * K + gk);
                } else {
                    float t[4] = {0.f, 0.f, 0.f, 0.f};
                    #pragma unroll
                    for (int q = 0; q < 4; q++) if (gk + q < K) t[q] = B[(size_t)gn * K + gk + q];
                    v = make_float4(t[0], t[1], t[2], t[3]);
                }
            }
            Bs[lkq + 0][lrow] = v.x; Bs[lkq + 1][lrow] = v.y;
            Bs[lkq + 2][lrow] = v.z; Bs[lkq + 3][lrow] = v.w;
        }
        __syncthreads();

        #pragma unroll
        for (int k = 0; k < BK; k++) {
            float4 a = *reinterpret_cast<const float4*>(&As[k][ty * 4]);
            float4 b = *reinterpret_cast<const float4*>(&Bs[k][tx * 4]);
            acc[0][0] += a.x * b.x; acc[0][1] += a.x * b.y; acc[0][2] += a.x * b.z; acc[0][3] += a.x * b.w;
            acc[1][0] += a.y * b.x; acc[1][1] += a.y * b.y; acc[1][2] += a.y * b.z; acc[1][3] += a.y * b.w;
            acc[2][0] += a.z * b.x; acc[2][1] += a.z * b.y; acc[2][2] += a.z * b.z; acc[2][3] += a.z * b.w;
            acc[3][0] += a.w * b.x; acc[3][1] += a.w * b.y; acc[3][2] += a.w * b.z; acc[3][3] += a.w * b.w;
        }
        __syncthreads();
    }

    #pragma unroll
    for (int i = 0; i < 4; i++) {
        int gm = m0 + ty * 4 + i;
        if (gm >= M) continue;
        #pragma unroll
        for (int j = 0; j < 4; j++) {
            int gn = n0 + tx * 4 + j;
            if (gn >= N) continue;
            float v = acc[i][j];
            if (bias) v += bias[gn];
            if (mode >= 1) v = fmaxf(v, 0.f);
            if (mode == 2) v += R[(size_t)gm * N + gn];
            C[(size_t)gm * N + gn] = v;
        }
    }
}

// ---------------------------------------------------------------------------
// Fused LSTM step: gates = h_prev @ Whh^T + (bih+bhh) + gather(xproj), then
// elementwise c/h update. CTA tile: 64 batch rows x (16 hidden x 4 gates).
// Local B column c maps to gate=(c&3), hid = nb*16 + (c>>2), so each thread's
// 4 accumulator columns are the i/f/g/o of one hidden unit.
// ---------------------------------------------------------------------------
__global__ __launch_bounds__(256) void lstm_step_kernel(
    const float* __restrict__ Hprev, float* __restrict__ Hnext,
    float* __restrict__ Cst,
    const float* __restrict__ Whh,
    const float* __restrict__ bih, const float* __restrict__ bhh,
    const float* __restrict__ xproj,
    const int* __restrict__ starts, const int* __restrict__ sizes,
    int t, int B)
{
    __shared__ float As[BK][BM];
    __shared__ float Bs[BK][BN];

    const int nb = blockIdx.x;        // hidden slice: 16 units
    const int m0 = blockIdx.y * BM;
    const int tid = threadIdx.x;
    const int tx = tid & 15;
    const int ty = tid >> 4;
    const int lrow = tid >> 2;        // local B col / A row 0..63
    const int lkq  = (tid & 3) * 4;

    // Whh row for local column lrow
    const int brow = (lrow & 3) * HID + nb * 16 + (lrow >> 2);

    float acc[4][4] = {};

    for (int k0 = 0; k0 < HID; k0 += BK) {
        {
            int gm = m0 + lrow;
            float4 v = make_float4(0.f, 0.f, 0.f, 0.f);
            if (gm < B) v = *reinterpret_cast<const float4*>(Hprev + (size_t)gm * HID + k0 + lkq);
            As[lkq + 0][lrow] = v.x; As[lkq + 1][lrow] = v.y;
            As[lkq + 2][lrow] = v.z; As[lkq + 3][lrow] = v.w;
        }
        {
            float4 v = *reinterpret_cast<const float4*>(Whh + (size_t)brow * HID + k0 + lkq);
            Bs[lkq + 0][lrow] = v.x; Bs[lkq + 1][lrow] = v.y;
            Bs[lkq + 2][lrow] = v.z; Bs[lkq + 3][lrow] = v.w;
        }
        __syncthreads();

        #pragma unroll
        for (int k = 0; k < BK; k++) {
            float4 a = *reinterpret_cast<const float4*>(&As[k][ty * 4]);
            float4 b = *reinterpret_cast<const float4*>(&Bs[k][tx * 4]);
            acc[0][0] += a.x * b.x; acc[0][1] += a.x * b.y; acc[0][2] += a.x * b.z; acc[0][3] += a.x * b.w;
            acc[1][0] += a.y * b.x; acc[1][1] += a.y * b.y; acc[1][2] += a.y * b.z; acc[1][3] += a.y * b.w;
            acc[2][0] += a.z * b.x; acc[2][1] += a.z * b.y; acc[2][2] += a.z * b.z; acc[2][3] += a.z * b.w;
            acc[3][0] += a.w * b.x; acc[3][1] += a.w * b.y; acc[3][2] += a.w * b.z; acc[3][3] += a.w * b.w;
        }
        __syncthreads();
    }

    const int hid = nb * 16 + tx;
    const float bI = bih[0 * HID + hid] + bhh[0 * HID + hid];
    const float bF = bih[1 * HID + hid] + bhh[1 * HID + hid];
    const float bG = bih[2 * HID + hid] + bhh[2 * HID + hid];
    const float bO = bih[3 * HID + hid] + bhh[3 * HID + hid];

    #pragma unroll
    for (int i = 0; i < 4; i++) {
        int b = m0 + ty * 4 + i;
        if (b >= B) continue;
        float gi = acc[i][0] + bI;
        float gf = acc[i][1] + bF;
        float gg = acc[i][2] + bG;
        float go = acc[i][3] + bO;
        int sz = sizes[b];
        if (t < sz) {
            size_t base = (size_t)(starts[b] + t) * GATES;
            gi += xproj[base + 0 * HID + hid];
            gf += xproj[base + 1 * HID + hid];
            gg += xproj[base + 2 * HID + hid];
            go += xproj[base + 3 * HID + hid];
        }
        size_t idx = (size_t)b * HID + hid;
        float cold = Cst[idx];
        float is = 1.f / (1.f + expf(-gi));
        float fs = 1.f / (1.f + expf(-gf));
        float gt = tanhf(gg);
        float os = 1.f / (1.f + expf(-go));
        float cn = fs * cold + is * gt;
        Cst[idx] = cn;
        Hnext[idx] = os * tanhf(cn);
    }
}

// ---------------------------------------------------------------------------
// Decoder: out[b] = dot(X[b,:], Wd) + bd   (warp per row)
// ---------------------------------------------------------------------------
__global__ void decoder_kernel(const float* __restrict__ X, const float* __restrict__ Wd,
                               const float* __restrict__ bd, float* __restrict__ out, int B)
{
    int warp = (blockIdx.x * blockDim.x + threadIdx.x) >> 5;
    int lane = threadIdx.x & 31;
    if (warp >= B) return;
    const float4* row = reinterpret_cast<const float4*>(X + (size_t)warp * HID);
    const float4* w   = reinterpret_cast<const float4*>(Wd);
    float s = 0.f;
    #pragma unroll
    for (int i = lane; i < HID / 4; i += 32) {
        float4 a = row[i], bw = w[i];
        s += a.x * bw.x + a.y * bw.y + a.z * bw.z + a.w * bw.w;
    }
    #pragma unroll
    for (int o = 16; o > 0; o >>= 1) s += __shfl_down_sync(0xffffffffu, s, o);
    if (lane == 0) out[warp] = s + bd[0];
}

// ---------------------------------------------------------------------------
// Launch
// ---------------------------------------------------------------------------
extern "C" void kernel_launch(void* const* d_in, const int* in_sizes, int n_in,
                              void* d_out, int out_size)
{
    const int*   sizes = (const int*)  d_in[0];
    const float* feat  = (const float*)d_in[1];
    const float* We0   = (const float*)d_in[2];
    const float* be0   = (const float*)d_in[3];
    const float* We1   = (const float*)d_in[4];
    const float* be1   = (const float*)d_in[5];
    const float* Wih   = (const float*)d_in[6];
    const float* bih   = (const float*)d_in[7];
    const float* Whh   = (const float*)d_in[8];
    const float* bhh   = (const float*)d_in[9];
    const float* Wl0   = (const float*)d_in[10];
    const float* bl0   = (const float*)d_in[11];
    const float* Wl1   = (const float*)d_in[12];
    const float* bl1   = (const float*)d_in[13];
    const float* Wd    = (const float*)d_in[14];
    const float* bd    = (const float*)d_in[15];

    const int B  = in_sizes[0];
    const int K0 = in_sizes[2] / HID;     // IN_DIM (164)
    const int T  = in_sizes[1] / K0;

    float *x1, *x2, *xproj, *h0, *h1, *cst, *t0, *t1;
    int *starts;
    cudaGetSymbolAddress((void**)&x1,    g_x1);
    cudaGetSymbolAddress((void**)&x2,    g_x2);
    cudaGetSymbolAddress((void**)&xproj, g_xproj);
    cudaGetSymbolAddress((void**)&h0,    g_h0);
    cudaGetSymbolAddress((void**)&h1,    g_h1);
    cudaGetSymbolAddress((void**)&cst,   g_c);
    cudaGetSymbolAddress((void**)&t0,    g_t0);
    cudaGetSymbolAddress((void**)&t1,    g_t1);
    cudaGetSymbolAddress((void**)&starts, g_starts);

    scan_starts_kernel<<<1, BMAX>>>(sizes, starts, B);

    int nz = B * HID;
    fill_zero_kernel<<<(nz + 255) / 256, 256>>>(h0, nz);
    fill_zero_kernel<<<(nz + 255) / 256, 256>>>(cst, nz);

    int mblk = (T + BM - 1) / BM;
    // encoder layer 0: x1 = relu(feat @ We0^T + be0)
    gemm_nt_kernel<<<dim3(HID / BN, mblk), 256>>>(feat, We0, be0, nullptr, x1, T, HID, K0, 1);
    // encoder layer 1: x2 = relu(x1 @ We1^T + be1)
    gemm_nt_kernel<<<dim3(HID / BN, mblk), 256>>>(x1, We1, be1, nullptr, x2, T, HID, HID, 1);
    // x projection: xproj = x2 @ Wih^T   (bias added inside the step)
    gemm_nt_kernel<<<dim3(GATES / BN, mblk), 256>>>(x2, Wih, nullptr, nullptr, xproj, T, GATES, HID, 0);

    // LSTM: 128 fused steps, h ping-pong
    for (int t = 0; t < MAXLEN; t++) {
        const float* hp = (t & 1) ? h1 : h0;
        float*       hn = (t & 1) ? h0 : h1;
        lstm_step_kernel<<<dim3(HID / 16, B / BM), 256>>>(hp, hn, cst, Whh, bih, bhh,
                                                          xproj, starts, sizes, t, B);
    }
    const float* hf = h0;  // MAXLEN even -> final h in h0

    // residual MLPs
    gemm_nt_kernel<<<dim3(HID / BN, B / BM), 256>>>(hf, Wl0, bl0, hf, t0, B, HID, HID, 2);
    gemm_nt_kernel<<<dim3(HID / BN, B / BM), 256>>>(t0, Wl1, bl1, t0, t1, B, HID, HID, 2);

    // decoder
    decoder_kernel<<<(B * 32 + 255) / 256, 256>>>(t1, Wd, bd, (float*)d_out, B);
}